// round 2
// baseline (speedup 1.0000x reference)
#include <cuda_runtime.h>
#include <math.h>

#define N0    260000
#define N1    10240
#define BATCH 1024
#define E0    256000
#define E1    10240
#define IN_C  602
#define HID   256
#define OUT_C 41

// Scratch (no cudaMalloc allowed)
__device__ float g_agg0[N1 * IN_C];   // [10240, 602]  ~24.7 MB
__device__ float g_h[N1 * HID];       // [10240, 256]  ~10.5 MB

__device__ __forceinline__ int lower_bound_i(const int* __restrict__ a, int n, int v) {
    int lo = 0, hi = n;
    while (lo < hi) {
        int mid = (lo + hi) >> 1;
        if (a[mid] < v) lo = mid + 1; else hi = mid;
    }
    return lo;
}

// ---------------------------------------------------------------------------
// Kernel 1: segment-mean aggregation, layer 0.
// One CTA per target node t. dst0 is sorted -> binary search edge range.
// 128 threads; each thread owns channels tid, tid+128, ..., tid+512.
// ---------------------------------------------------------------------------
__global__ void agg0_kernel(const float* __restrict__ x,
                            const int* __restrict__ src,
                            const int* __restrict__ dst) {
    const int t   = blockIdx.x;
    const int tid = threadIdx.x;

    const int s = lower_bound_i(dst, E0, t);
    const int e = lower_bound_i(dst, E0, t + 1);

    __shared__ int s_src[128];

    float acc0 = 0.f, acc1 = 0.f, acc2 = 0.f, acc3 = 0.f, acc4 = 0.f;

    for (int base = s; base < e; base += 128) {
        int n = e - base; if (n > 128) n = 128;
        if (tid < n) s_src[tid] = src[base + tid];
        __syncthreads();
        for (int i = 0; i < n; i++) {
            const float* row = x + (long)s_src[i] * IN_C;
            acc0 += row[tid];
            acc1 += row[tid + 128];
            acc2 += row[tid + 256];
            acc3 += row[tid + 384];
            if (tid + 512 < IN_C) acc4 += row[tid + 512];
        }
        __syncthreads();
    }

    const float inv = 1.0f / (float)((e - s) > 1 ? (e - s) : 1);
    float* out = g_agg0 + (long)t * IN_C;
    out[tid]        = acc0 * inv;
    out[tid + 128]  = acc1 * inv;
    out[tid + 256]  = acc2 * inv;
    out[tid + 384]  = acc3 * inv;
    if (tid + 512 < IN_C) out[tid + 512] = acc4 * inv;
}

// ---------------------------------------------------------------------------
// Kernel 2: h = relu( agg0 @ W_l0 + x[:N1] @ W_r0 + b_l0 )
// Fused as one GEMM with virtual K = 2*602 = 1204:
//   k <  602 : A = g_agg0, B = W_l0
//   k >= 602 : A = x      , B = W_r0
// Tiled SGEMM: 128x128 block tile, BK=8, 256 threads, 8x8 per-thread tile.
// ---------------------------------------------------------------------------
#define BM 128
#define BN 128
#define BK 8

__global__ void __launch_bounds__(256) gemm_h_kernel(const float* __restrict__ x,
                                                     const float* __restrict__ Wl,
                                                     const float* __restrict__ bl,
                                                     const float* __restrict__ Wr) {
    __shared__ float As[BK][BM];
    __shared__ float Bs[BK][BN];

    const int tid = threadIdx.x;
    const int tx  = tid & 15;   // 0..15
    const int ty  = tid >> 4;   // 0..15
    const int m0  = blockIdx.y * BM;
    const int n0  = blockIdx.x * BN;

    float acc[8][8];
    #pragma unroll
    for (int i = 0; i < 8; i++)
        #pragma unroll
        for (int j = 0; j < 8; j++) acc[i][j] = 0.f;

    const int KK = 2 * IN_C;  // 1204

    for (int k0 = 0; k0 < KK; k0 += BK) {
        // ---- load A tile (BM x BK), transposed into As[k][m] ----
        #pragma unroll
        for (int j = 0; j < 4; j++) {
            int idx = tid * 4 + j;          // 0..1023
            int m   = idx >> 3;             // 0..127
            int k   = idx & 7;              // 0..7
            int kg  = k0 + k;
            float v = 0.f;
            if (kg < IN_C)
                v = g_agg0[(long)(m0 + m) * IN_C + kg];
            else if (kg < KK)
                v = x[(long)(m0 + m) * IN_C + (kg - IN_C)];
            As[k][m] = v;
        }
        // ---- load B tile (BK x BN) ----
        #pragma unroll
        for (int j = 0; j < 4; j++) {
            int idx = tid * 4 + j;          // 0..1023
            int k   = idx >> 7;             // 0..7
            int n   = idx & 127;            // 0..127
            int kg  = k0 + k;
            float v = 0.f;
            if (kg < IN_C)
                v = Wl[(long)kg * HID + (n0 + n)];
            else if (kg < KK)
                v = Wr[(long)(kg - IN_C) * HID + (n0 + n)];
            Bs[k][n] = v;
        }
        __syncthreads();

        #pragma unroll
        for (int kk = 0; kk < BK; kk++) {
            float a[8], b[8];
            #pragma unroll
            for (int i = 0; i < 4; i++) {
                a[i]     = As[kk][ty * 4 + i];
                a[i + 4] = As[kk][64 + ty * 4 + i];
            }
            #pragma unroll
            for (int j = 0; j < 4; j++) {
                b[j]     = Bs[kk][tx * 4 + j];
                b[j + 4] = Bs[kk][64 + tx * 4 + j];
            }
            #pragma unroll
            for (int i = 0; i < 8; i++)
                #pragma unroll
                for (int j = 0; j < 8; j++)
                    acc[i][j] += a[i] * b[j];
        }
        __syncthreads();
    }

    // ---- epilogue: + bias, ReLU, store h ----
    #pragma unroll
    for (int i = 0; i < 8; i++) {
        int mi = (i < 4) ? (ty * 4 + i) : (64 + ty * 4 + (i - 4));
        int m  = m0 + mi;
        #pragma unroll
        for (int j = 0; j < 8; j++) {
            int nj = (j < 4) ? (tx * 4 + j) : (64 + tx * 4 + (j - 4));
            int n  = n0 + nj;
            float v = acc[i][j] + bl[n];
            g_h[(long)m * HID + n] = fmaxf(v, 0.f);
        }
    }
}

// ---------------------------------------------------------------------------
// Kernel 3: fused layer 1 — segment-mean over h, linear, log_softmax.
// One CTA per output row b (1024 CTAs, 128 threads).
// ---------------------------------------------------------------------------
__global__ void layer1_kernel(const float* __restrict__ Wl1,
                              const float* __restrict__ bl1,
                              const float* __restrict__ Wr1,
                              const int* __restrict__ src,
                              const int* __restrict__ dst,
                              float* __restrict__ out) {
    const int b   = blockIdx.x;
    const int tid = threadIdx.x;   // 128

    __shared__ float s_agg[HID];
    __shared__ float s_h[HID];
    __shared__ int   s_src[128];
    __shared__ float s_logits[OUT_C];
    __shared__ float s_red[2];

    const int s = lower_bound_i(dst, E1, b);
    const int e = lower_bound_i(dst, E1, b + 1);

    float a0 = 0.f, a1 = 0.f;
    for (int base = s; base < e; base += 128) {
        int n = e - base; if (n > 128) n = 128;
        if (tid < n) s_src[tid] = src[base + tid];
        __syncthreads();
        for (int i = 0; i < n; i++) {
            const float* row = g_h + (long)s_src[i] * HID;
            a0 += row[tid];
            a1 += row[tid + 128];
        }
        __syncthreads();
    }

    const float inv = 1.0f / (float)((e - s) > 1 ? (e - s) : 1);
    s_agg[tid]       = a0 * inv;
    s_agg[tid + 128] = a1 * inv;
    s_h[tid]         = g_h[(long)b * HID + tid];
    s_h[tid + 128]   = g_h[(long)b * HID + tid + 128];
    __syncthreads();

    if (tid < OUT_C) {
        float acc = bl1[tid];
        #pragma unroll 4
        for (int k = 0; k < HID; k++) {
            acc += s_agg[k] * Wl1[k * OUT_C + tid];
            acc += s_h[k]   * Wr1[k * OUT_C + tid];
        }
        s_logits[tid] = acc;
    }
    __syncthreads();

    if (tid == 0) {
        float mx = -1e30f;
        for (int j = 0; j < OUT_C; j++) mx = fmaxf(mx, s_logits[j]);
        float sum = 0.f;
        for (int j = 0; j < OUT_C; j++) sum += expf(s_logits[j] - mx);
        s_red[0] = mx;
        s_red[1] = logf(sum);
    }
    __syncthreads();

    if (tid < OUT_C)
        out[b * OUT_C + tid] = s_logits[tid] - s_red[0] - s_red[1];
}

// ---------------------------------------------------------------------------
extern "C" void kernel_launch(void* const* d_in, const int* in_sizes, int n_in,
                              void* d_out, int out_size) {
    const float* x    = (const float*)d_in[0];
    const float* W_l0 = (const float*)d_in[1];
    const float* b_l0 = (const float*)d_in[2];
    const float* W_r0 = (const float*)d_in[3];
    const float* W_l1 = (const float*)d_in[4];
    const float* b_l1 = (const float*)d_in[5];
    const float* W_r1 = (const float*)d_in[6];
    const int*   src0 = (const int*)d_in[7];
    const int*   dst0 = (const int*)d_in[8];
    const int*   src1 = (const int*)d_in[9];
    const int*   dst1 = (const int*)d_in[10];
    float* out = (float*)d_out;

    agg0_kernel<<<N1, 128>>>(x, src0, dst0);
    gemm_h_kernel<<<dim3(HID / BN, N1 / BM), 256>>>(x, W_l0, b_l0, W_r0);
    layer1_kernel<<<BATCH, 128>>>(W_l1, b_l1, W_r1, src1, dst1, out);
}

// round 5
// speedup vs baseline: 2.0653x; 2.0653x over previous
#include <cuda_runtime.h>
#include <math.h>
#include <stdint.h>

#define N0    260000
#define N1    10240
#define BATCH 1024
#define E0    256000
#define E1    10240
#define IN_C  602
#define HID   256
#define OUT_C 41
#define KK    1204
#define KPAD  1216

// Scratch (no cudaMalloc allowed)
__device__ float g_agg0[(long)N1 * IN_C];   // [10240, 602]
__device__ float g_h[(long)N1 * HID];       // [10240, 256]
__device__ float g_Wt[HID * KPAD];          // [256, 1216] = (W_l0 ; W_r0)^T, zero-padded

__device__ __forceinline__ int lower_bound_i(const int* __restrict__ a, int n, int v) {
    int lo = 0, hi = n;
    while (lo < hi) {
        int mid = (lo + hi) >> 1;
        if (a[mid] < v) lo = mid + 1; else hi = mid;
    }
    return lo;
}

__device__ __forceinline__ uint32_t f2tf32(float f) {
    uint32_t r; asm("cvt.rna.tf32.f32 %0, %1;" : "=r"(r) : "f"(f)); return r;
}

__device__ __forceinline__ void mma8(float* d, const uint32_t* a, const uint32_t* b) {
    asm volatile("mma.sync.aligned.m16n8k8.row.col.f32.tf32.tf32.f32 "
        "{%0,%1,%2,%3}, {%4,%5,%6,%7}, {%8,%9}, {%0,%1,%2,%3};"
        : "+f"(d[0]), "+f"(d[1]), "+f"(d[2]), "+f"(d[3])
        : "r"(a[0]), "r"(a[1]), "r"(a[2]), "r"(a[3]), "r"(b[0]), "r"(b[1]));
}

// ---------------------------------------------------------------------------
// Kernel 0: tiled transpose of (W_l0 ; W_r0) -> g_Wt[n][k], K padded w/ zeros
// ---------------------------------------------------------------------------
__global__ void wt_kernel(const float* __restrict__ Wl, const float* __restrict__ Wr) {
    __shared__ float tile[32][33];
    const int kb = blockIdx.x * 32;
    const int nb = blockIdx.y * 32;
    const int tx = threadIdx.x, ty = threadIdx.y;   // 32 x 8

    #pragma unroll
    for (int i = 0; i < 4; i++) {
        int k = kb + ty + i * 8;
        float v = 0.f;
        if (k < IN_C)      v = Wl[k * HID + nb + tx];
        else if (k < KK)   v = Wr[(k - IN_C) * HID + nb + tx];
        tile[ty + i * 8][tx] = v;
    }
    __syncthreads();
    #pragma unroll
    for (int i = 0; i < 4; i++) {
        int n = nb + ty + i * 8;
        g_Wt[n * KPAD + kb + tx] = tile[tx][ty + i * 8];
    }
}

// ---------------------------------------------------------------------------
// Kernel 1: segment-mean aggregation (layer 0), float2 loads.
// ---------------------------------------------------------------------------
__global__ void agg0_kernel(const float* __restrict__ x,
                            const int* __restrict__ src,
                            const int* __restrict__ dst) {
    const int t   = blockIdx.x;
    const int tid = threadIdx.x;   // 128

    const int s = lower_bound_i(dst, E0, t);
    const int e = lower_bound_i(dst, E0, t + 1);

    __shared__ int s_src[128];

    float2 a0 = {0.f, 0.f}, a1 = {0.f, 0.f}, a2 = {0.f, 0.f};
    const bool has3 = (tid < 301 - 256);   // 602 floats = 301 float2

    for (int base = s; base < e; base += 128) {
        int n = e - base; if (n > 128) n = 128;
        if (tid < n) s_src[tid] = src[base + tid];
        __syncthreads();
        for (int i = 0; i < n; i++) {
            const float2* row = (const float2*)(x + (long)s_src[i] * IN_C);
            float2 v0 = row[tid];
            float2 v1 = row[tid + 128];
            a0.x += v0.x; a0.y += v0.y;
            a1.x += v1.x; a1.y += v1.y;
            if (has3) {
                float2 v2 = row[tid + 256];
                a2.x += v2.x; a2.y += v2.y;
            }
        }
        __syncthreads();
    }

    const float inv = 1.0f / (float)((e - s) > 1 ? (e - s) : 1);
    float2* out = (float2*)(g_agg0 + (long)t * IN_C);
    float2 w;
    w.x = a0.x * inv; w.y = a0.y * inv; out[tid] = w;
    w.x = a1.x * inv; w.y = a1.y * inv; out[tid + 128] = w;
    if (has3) { w.x = a2.x * inv; w.y = a2.y * inv; out[tid + 256] = w; }
}

// ---------------------------------------------------------------------------
// Kernel 2: h = relu( [agg0 | x] @ Wt^T + b )  via tf32 mma.sync
// BM=128, BN=128, BK=16, 256 threads (8 warps, 2x4), cp.async double buffer.
// ---------------------------------------------------------------------------
#define BM   128
#define BN   128
#define BKT  16
#define CS   1032                 // chunk (k8) stride in floats (pad kills STS conflicts)
#define BUF  (2 * CS)             // 2 k8-chunks per BK=16 tile
#define NT_K (KPAD / BKT)         // 76 tiles

__global__ void __launch_bounds__(256) gemm_h_kernel(const float* __restrict__ x,
                                                     const float* __restrict__ bl) {
    __shared__ float As[2 * BUF];
    __shared__ float Bs[2 * BUF];

    const int tid  = threadIdx.x;
    const int m0   = blockIdx.y * BM;
    const int n0   = blockIdx.x * BN;
    const int wid  = tid >> 5;
    const int lane = tid & 31;
    const int g    = lane >> 2;     // 0..7
    const int t    = lane & 3;      // 0..3
    const int wm   = (wid >> 2) * 64;   // warp m offset (0/64)
    const int wn   = (wid & 3) * 32;    // warp n offset

    float acc[4][4][4];
    #pragma unroll
    for (int i = 0; i < 4; i++)
        #pragma unroll
        for (int j = 0; j < 4; j++)
            #pragma unroll
            for (int q = 0; q < 4; q++) acc[i][j][q] = 0.f;

    const uint32_t sA = (uint32_t)__cvta_generic_to_shared(As);
    const uint32_t sB = (uint32_t)__cvta_generic_to_shared(Bs);

    // precompute per-thread load coords: 4 (pair) slots, each pair = 2 floats
    // p = i*256 + tid ; m/n = p>>3 ; kp = p&7 ; k within tile = 2*kp
    auto load_tile = [&](int tt, int b) {
        const int k0 = tt * BKT;
        #pragma unroll
        for (int i = 0; i < 4; i++) {
            int p  = i * 256 + tid;
            int m  = p >> 3;
            int kp = p & 7;
            int kg = k0 + 2 * kp;
            int c  = kp >> 2;
            int kq = (2 * kp) & 7;
            uint32_t off = (uint32_t)((b * BUF + c * CS + m * 8 + kq) * 4);

            // ---- A ----
            const float* srcA;
            int szA = 8;
            if (kg < IN_C)       srcA = g_agg0 + (long)(m0 + m) * IN_C + kg;
            else if (kg < KK)    srcA = x + (long)(m0 + m) * IN_C + (kg - IN_C);
            else               { srcA = x; szA = 0; }
            asm volatile("cp.async.ca.shared.global [%0], [%1], 8, %2;"
                         :: "r"(sA + off), "l"(srcA), "r"(szA));

            // ---- B ---- (Wt is KPAD-wide, zero padded -> unconditional)
            const float* srcB = g_Wt + (long)(n0 + m) * KPAD + kg;
            asm volatile("cp.async.ca.shared.global [%0], [%1], 8, 8;"
                         :: "r"(sB + off), "l"(srcB));
        }
    };

    load_tile(0, 0);
    asm volatile("cp.async.commit_group;");

    for (int tt = 0; tt < NT_K; tt++) {
        const int cb = tt & 1;
        if (tt + 1 < NT_K) {
            load_tile(tt + 1, (tt + 1) & 1);
            asm volatile("cp.async.commit_group;");
            asm volatile("cp.async.wait_group 1;");
        } else {
            asm volatile("cp.async.wait_group 0;");
        }
        __syncthreads();

        #pragma unroll
        for (int c = 0; c < 2; c++) {
            const float* Ab = As + cb * BUF + c * CS;
            const float* Bb = Bs + cb * BUF + c * CS;

            uint32_t af[4][4];
            #pragma unroll
            for (int mt = 0; mt < 4; mt++) {
                float2 lo = *(const float2*)(Ab + (wm + mt * 16 + g) * 8 + 2 * t);
                float2 hi = *(const float2*)(Ab + (wm + mt * 16 + g + 8) * 8 + 2 * t);
                af[mt][0] = f2tf32(lo.x);
                af[mt][2] = f2tf32(lo.y);
                af[mt][1] = f2tf32(hi.x);
                af[mt][3] = f2tf32(hi.y);
            }
            uint32_t bf[4][2];
            #pragma unroll
            for (int nt = 0; nt < 4; nt++) {
                float2 bv = *(const float2*)(Bb + (wn + nt * 8 + g) * 8 + 2 * t);
                bf[nt][0] = f2tf32(bv.x);
                bf[nt][1] = f2tf32(bv.y);
            }
            #pragma unroll
            for (int mt = 0; mt < 4; mt++)
                #pragma unroll
                for (int nt = 0; nt < 4; nt++)
                    mma8(acc[mt][nt], af[mt], bf[nt]);
        }
        __syncthreads();
    }

    // epilogue: + bias, relu, store h (float2, 8B aligned since col even)
    #pragma unroll
    for (int nt = 0; nt < 4; nt++) {
        const int col = n0 + wn + nt * 8 + 2 * t;
        const float b0v = bl[col], b1v = bl[col + 1];
        #pragma unroll
        for (int mt = 0; mt < 4; mt++) {
            const int r0 = m0 + wm + mt * 16 + g;
            float2 v;
            v.x = fmaxf(acc[mt][nt][0] + b0v, 0.f);
            v.y = fmaxf(acc[mt][nt][1] + b1v, 0.f);
            *(float2*)&g_h[(long)r0 * HID + col] = v;
            v.x = fmaxf(acc[mt][nt][2] + b0v, 0.f);
            v.y = fmaxf(acc[mt][nt][3] + b1v, 0.f);
            *(float2*)&g_h[(long)(r0 + 8) * HID + col] = v;
        }
    }
}

// ---------------------------------------------------------------------------
// Kernel 3: fused layer 1 — segment-mean over h, linear, log_softmax.
// ---------------------------------------------------------------------------
__global__ void layer1_kernel(const float* __restrict__ Wl1,
                              const float* __restrict__ bl1,
                              const float* __restrict__ Wr1,
                              const int* __restrict__ src,
                              const int* __restrict__ dst,
                              float* __restrict__ out) {
    const int b   = blockIdx.x;
    const int tid = threadIdx.x;   // 128

    __shared__ float s_agg[HID];
    __shared__ float s_h[HID];
    __shared__ int   s_src[128];
    __shared__ float s_logits[OUT_C];
    __shared__ float s_red[2];

    const int s = lower_bound_i(dst, E1, b);
    const int e = lower_bound_i(dst, E1, b + 1);

    float a0 = 0.f, a1 = 0.f;
    for (int base = s; base < e; base += 128) {
        int n = e - base; if (n > 128) n = 128;
        if (tid < n) s_src[tid] = src[base + tid];
        __syncthreads();
        for (int i = 0; i < n; i++) {
            const float* row = g_h + (long)s_src[i] * HID;
            a0 += row[tid];
            a1 += row[tid + 128];
        }
        __syncthreads();
    }

    const float inv = 1.0f / (float)((e - s) > 1 ? (e - s) : 1);
    s_agg[tid]       = a0 * inv;
    s_agg[tid + 128] = a1 * inv;
    s_h[tid]         = g_h[(long)b * HID + tid];
    s_h[tid + 128]   = g_h[(long)b * HID + tid + 128];
    __syncthreads();

    if (tid < OUT_C) {
        float acc = bl1[tid];
        #pragma unroll 4
        for (int k = 0; k < HID; k++) {
            acc += s_agg[k] * Wl1[k * OUT_C + tid];
            acc += s_h[k]   * Wr1[k * OUT_C + tid];
        }
        s_logits[tid] = acc;
    }
    __syncthreads();

    if (tid == 0) {
        float mx = -1e30f;
        for (int j = 0; j < OUT_C; j++) mx = fmaxf(mx, s_logits[j]);
        float sum = 0.f;
        for (int j = 0; j < OUT_C; j++) sum += expf(s_logits[j] - mx);
        s_red[0] = mx;
        s_red[1] = logf(sum);
    }
    __syncthreads();

    if (tid < OUT_C)
        out[b * OUT_C + tid] = s_logits[tid] - s_red[0] - s_red[1];
}

// ---------------------------------------------------------------------------
extern "C" void kernel_launch(void* const* d_in, const int* in_sizes, int n_in,
                              void* d_out, int out_size) {
    const float* x    = (const float*)d_in[0];
    const float* W_l0 = (const float*)d_in[1];
    const float* b_l0 = (const float*)d_in[2];
    const float* W_r0 = (const float*)d_in[3];
    const float* W_l1 = (const float*)d_in[4];
    const float* b_l1 = (const float*)d_in[5];
    const float* W_r1 = (const float*)d_in[6];
    const int*   src0 = (const int*)d_in[7];
    const int*   dst0 = (const int*)d_in[8];
    const int*   src1 = (const int*)d_in[9];
    const int*   dst1 = (const int*)d_in[10];
    float* out = (float*)d_out;

    wt_kernel<<<dim3(KPAD / 32, HID / 32), dim3(32, 8)>>>(W_l0, W_r0);
    agg0_kernel<<<N1, 128>>>(x, src0, dst0);
    gemm_h_kernel<<<dim3(HID / BN, N1 / BM), 256>>>(x, b_l0);
    layer1_kernel<<<BATCH, 128>>>(W_l1, b_l1, W_r1, src1, dst1, out);
}